// round 1
// baseline (speedup 1.0000x reference)
#include <cuda_runtime.h>
#include <math.h>

// Problem constants
#define BB 8
#define NN 1024
#define CC 512
#define HEADS 8
#define HD 64
#define T_ROWS 3969
#define M_ROWS (BB * NN)      // 8192
#define CPB_HIDDEN 512

// ----------------------------------------------------------------------------
// Scratch (static device globals; no runtime allocation)
// ----------------------------------------------------------------------------
__device__ float g_qkv[(size_t)M_ROWS * 3 * CC];            // 8192 x 1536
__device__ float g_q[(size_t)BB * HEADS * NN * HD];          // normalized+scaled q
__device__ float g_k[(size_t)BB * HEADS * NN * HD];          // normalized k
__device__ float g_v[(size_t)BB * HEADS * NN * HD];          // v (re-laid-out)
__device__ float g_bias[T_ROWS * HEADS];                     // CPB table output
__device__ float g_attn[(size_t)M_ROWS * CC];                // attention output (b,n,h,d)

// ----------------------------------------------------------------------------
// SGEMM: C[M,N] = A[M,K] @ W[N,K]^T + bias[N]
// 128x128 block tile, BK=8, 256 threads, 8x8 per thread.
// Requires M%128==0, N%128==0, K%8==0, K%4==0 (float4 loads).
// ----------------------------------------------------------------------------
__global__ __launch_bounds__(256) void sgemm_bias_kernel(
    const float* __restrict__ A, const float* __restrict__ W,
    const float* __restrict__ bias, float* __restrict__ C,
    int M, int N, int K)
{
    __shared__ float sA[8][128];
    __shared__ float sB[8][128];

    int tid = threadIdx.x;
    int m0 = blockIdx.y * 128;
    int n0 = blockIdx.x * 128;
    int row0 = (tid >> 4) * 8;     // 0..120
    int col0 = (tid & 15) * 8;     // 0..120

    int lr = tid >> 1;             // 0..127
    int lk = (tid & 1) * 4;        // 0 or 4

    const float* Ap = A + (size_t)(m0 + lr) * K + lk;
    const float* Wp = W + (size_t)(n0 + lr) * K + lk;

    float acc[8][8];
#pragma unroll
    for (int i = 0; i < 8; i++)
#pragma unroll
        for (int j = 0; j < 8; j++) acc[i][j] = 0.f;

    for (int k0 = 0; k0 < K; k0 += 8) {
        float4 av = *(const float4*)(Ap + k0);
        float4 wv = *(const float4*)(Wp + k0);
        sA[lk + 0][lr] = av.x; sA[lk + 1][lr] = av.y;
        sA[lk + 2][lr] = av.z; sA[lk + 3][lr] = av.w;
        sB[lk + 0][lr] = wv.x; sB[lk + 1][lr] = wv.y;
        sB[lk + 2][lr] = wv.z; sB[lk + 3][lr] = wv.w;
        __syncthreads();
#pragma unroll
        for (int kk = 0; kk < 8; kk++) {
            float a[8], b[8];
#pragma unroll
            for (int i = 0; i < 8; i++) a[i] = sA[kk][row0 + i];
#pragma unroll
            for (int j = 0; j < 8; j++) b[j] = sB[kk][col0 + j];
#pragma unroll
            for (int i = 0; i < 8; i++)
#pragma unroll
                for (int j = 0; j < 8; j++) acc[i][j] += a[i] * b[j];
        }
        __syncthreads();
    }

#pragma unroll
    for (int i = 0; i < 8; i++) {
        size_t out_row = (size_t)(m0 + row0 + i) * N + n0 + col0;
#pragma unroll
        for (int j = 0; j < 8; j++)
            C[out_row + j] = acc[i][j] + bias[n0 + col0 + j];
    }
}

// ----------------------------------------------------------------------------
// CPB MLP: for each table row t: hidden = relu(coords @ fc1^T + b1) (512),
// bias_tab[t][h] = hidden @ fc2[h] + b2[h].  One block per t, 512 threads.
// ----------------------------------------------------------------------------
__global__ __launch_bounds__(512) void cpb_kernel(
    const float* __restrict__ table,
    const float* __restrict__ fc1w, const float* __restrict__ fc1b,
    const float* __restrict__ fc2w, const float* __restrict__ fc2b)
{
    __shared__ float sh[CPB_HIDDEN];
    __shared__ float part[16];
    int t = blockIdx.x;
    int tid = threadIdx.x;

    float c0 = table[t * 2 + 0];
    float c1 = table[t * 2 + 1];
    float hv = c0 * fc1w[tid * 2 + 0] + c1 * fc1w[tid * 2 + 1] + fc1b[tid];
    sh[tid] = fmaxf(hv, 0.f);
    __syncthreads();

    int w = tid >> 5, lane = tid & 31;
    int head = w & 7, seg = w >> 3;
    float s = 0.f;
#pragma unroll
    for (int i = 0; i < 8; i++) {
        int j = seg * 256 + i * 32 + lane;
        s += sh[j] * fc2w[head * CPB_HIDDEN + j];
    }
#pragma unroll
    for (int off = 16; off; off >>= 1)
        s += __shfl_xor_sync(0xffffffffu, s, off);
    if (lane == 0) part[w] = s;
    __syncthreads();
    if (tid < 8) g_bias[t * 8 + tid] = part[tid] + part[tid + 8] + fc2b[tid];
}

// ----------------------------------------------------------------------------
// Prep: split qkv into per-(b,h) contiguous Q,K,V; L2-normalize q and k,
// q' = (q/||q|| + query_embedding[h]) * softplus(temp[h]) * seq_scale.
// One warp per (m,h) row. grid = 8192 blocks x 256 threads.
// ----------------------------------------------------------------------------
__global__ __launch_bounds__(256) void prep_kernel(
    const float* __restrict__ temperature,
    const float* __restrict__ query_emb,
    const float* __restrict__ seq_scale)
{
    int gid = blockIdx.x * 8 + (threadIdx.x >> 5);   // 0..65535 over (m,h)
    int lane = threadIdx.x & 31;
    int m = gid >> 3, h = gid & 7;
    int b = m >> 10, n = m & 1023;

    const float* src = g_qkv + (size_t)m * (3 * CC) + h * HD;
    float q0 = src[lane],           q1 = src[lane + 32];
    float k0 = src[CC + lane],      k1 = src[CC + lane + 32];
    float v0 = src[2 * CC + lane],  v1 = src[2 * CC + lane + 32];

    float sq = q0 * q0 + q1 * q1;
    float sk = k0 * k0 + k1 * k1;
#pragma unroll
    for (int off = 16; off; off >>= 1) {
        sq += __shfl_xor_sync(0xffffffffu, sq, off);
        sk += __shfl_xor_sync(0xffffffffu, sk, off);
    }
    float qinv = 1.f / fmaxf(sqrtf(sq), 1e-12f);
    float kinv = 1.f / fmaxf(sqrtf(sk), 1e-12f);

    float tv = temperature[h];
    float sp = (tv > 20.f) ? tv : log1pf(expf(tv));
    float scale = sp * seq_scale[0];

    size_t dst = ((size_t)(b * 8 + h) * NN + n) * HD;
    g_q[dst + lane]      = (q0 * qinv + query_emb[h * HD + lane]) * scale;
    g_q[dst + lane + 32] = (q1 * qinv + query_emb[h * HD + lane + 32]) * scale;
    g_k[dst + lane]      = k0 * kinv;
    g_k[dst + lane + 32] = k1 * kinv;
    g_v[dst + lane]      = v0;
    g_v[dst + lane + 32] = v1;
}

// ----------------------------------------------------------------------------
// Flash attention with gathered positional bias.
// Block = (b,h) x 64-query tile. 256 threads.
// Shared: sQ/sK/sV/sS each [64][65] floats (dynamic, 66560 B).
// Thread tile: 4 rows x 4 keys (scores) / 4 rows x 4 dims (output).
// ----------------------------------------------------------------------------
#define SMEM_PITCH 65
#define ATTN_SMEM (4 * 64 * SMEM_PITCH * 4)

__global__ __launch_bounds__(256) void attn_kernel(const int* __restrict__ relidx)
{
    extern __shared__ float sm[];
    float* sQ = sm;
    float* sK = sm + 64 * SMEM_PITCH;
    float* sV = sm + 2 * 64 * SMEM_PITCH;
    float* sS = sm + 3 * 64 * SMEM_PITCH;

    int bh = blockIdx.x;          // 0..63 (b*8+h)
    int qt = blockIdx.y;          // 0..15
    int h = bh & 7;
    int b = bh >> 3;
    int tid = threadIdx.x;
    int rgrp = tid >> 4;          // 0..15 -> rows rgrp*4..+3
    int kgrp = tid & 15;          // 0..15 -> keys/dims kgrp*4..+3
    int r0 = rgrp * 4, c0 = kgrp * 4;
    int q0g = qt * 64;

    // load Q tile (already normalized+scaled)
    const float* Qg = g_q + ((size_t)bh * NN + q0g) * HD;
    for (int i = tid; i < 1024; i += 256) {          // 1024 float4 units
        int row = i >> 4, d4 = (i & 15) << 2;
        float4 v = *(const float4*)(Qg + row * HD + d4);
        float* p = sQ + row * SMEM_PITCH + d4;
        p[0] = v.x; p[1] = v.y; p[2] = v.z; p[3] = v.w;
    }

    float mrow[4], lrow[4], o[4][4];
#pragma unroll
    for (int r = 0; r < 4; r++) {
        mrow[r] = -1e30f; lrow[r] = 0.f;
#pragma unroll
        for (int c = 0; c < 4; c++) o[r][c] = 0.f;
    }

    for (int kt = 0; kt < 16; kt++) {
        __syncthreads();   // prior PV reads done (and Q load on first iter)
        const float* Kg = g_k + ((size_t)bh * NN + kt * 64) * HD;
        const float* Vg = g_v + ((size_t)bh * NN + kt * 64) * HD;
        for (int i = tid; i < 1024; i += 256) {
            int row = i >> 4, d4 = (i & 15) << 2;
            float4 kv = *(const float4*)(Kg + row * HD + d4);
            float4 vv = *(const float4*)(Vg + row * HD + d4);
            float* pk = sK + row * SMEM_PITCH + d4;
            float* pv = sV + row * SMEM_PITCH + d4;
            pk[0] = kv.x; pk[1] = kv.y; pk[2] = kv.z; pk[3] = kv.w;
            pv[0] = vv.x; pv[1] = vv.y; pv[2] = vv.z; pv[3] = vv.w;
        }
        __syncthreads();

        // scores: 4x4 register tile
        float s[4][4];
#pragma unroll
        for (int r = 0; r < 4; r++)
#pragma unroll
            for (int c = 0; c < 4; c++) s[r][c] = 0.f;

#pragma unroll 8
        for (int d = 0; d < 64; d++) {
            float a[4], bb[4];
#pragma unroll
            for (int r = 0; r < 4; r++) a[r] = sQ[(r0 + r) * SMEM_PITCH + d];
#pragma unroll
            for (int c = 0; c < 4; c++) bb[c] = sK[(c0 + c) * SMEM_PITCH + d];
#pragma unroll
            for (int r = 0; r < 4; r++)
#pragma unroll
                for (int c = 0; c < 4; c++) s[r][c] += a[r] * bb[c];
        }

        // add gathered relative-position bias
#pragma unroll
        for (int r = 0; r < 4; r++) {
            const int* ip = relidx + (size_t)(q0g + r0 + r) * NN + kt * 64 + c0;
#pragma unroll
            for (int c = 0; c < 4; c++)
                s[r][c] += g_bias[ip[c] * 8 + h];
        }

        // online softmax update (16-lane row groups)
#pragma unroll
        for (int r = 0; r < 4; r++) {
            float mt = s[r][0];
#pragma unroll
            for (int c = 1; c < 4; c++) mt = fmaxf(mt, s[r][c]);
#pragma unroll
            for (int off = 8; off; off >>= 1)
                mt = fmaxf(mt, __shfl_xor_sync(0xffffffffu, mt, off, 16));
            float nm = fmaxf(mrow[r], mt);
            float corr = __expf(mrow[r] - nm);
            float ps = 0.f;
#pragma unroll
            for (int c = 0; c < 4; c++) {
                s[r][c] = __expf(s[r][c] - nm);
                ps += s[r][c];
            }
#pragma unroll
            for (int off = 8; off; off >>= 1)
                ps += __shfl_xor_sync(0xffffffffu, ps, off, 16);
            lrow[r] = lrow[r] * corr + ps;
            mrow[r] = nm;
#pragma unroll
            for (int c = 0; c < 4; c++) o[r][c] *= corr;
            // store p for PV
#pragma unroll
            for (int c = 0; c < 4; c++)
                sS[(r0 + r) * SMEM_PITCH + c0 + c] = s[r][c];
        }
        __syncthreads();

        // PV: o[4 rows][4 dims] += P[rows][64] @ V[64][dims]
#pragma unroll 8
        for (int k = 0; k < 64; k++) {
            float p4[4], v4[4];
#pragma unroll
            for (int r = 0; r < 4; r++) p4[r] = sS[(r0 + r) * SMEM_PITCH + k];
#pragma unroll
            for (int c = 0; c < 4; c++) v4[c] = sV[k * SMEM_PITCH + c0 + c];
#pragma unroll
            for (int r = 0; r < 4; r++)
#pragma unroll
                for (int c = 0; c < 4; c++) o[r][c] += p4[r] * v4[c];
        }
    }

    // epilogue: divide by softmax denom, write (b, n, h, d) layout
#pragma unroll
    for (int r = 0; r < 4; r++) {
        float inv = 1.f / lrow[r];
        size_t outp = ((size_t)b * NN + q0g + r0 + r) * CC + h * HD + c0;
#pragma unroll
        for (int c = 0; c < 4; c++)
            g_attn[outp + c] = o[r][c] * inv;
    }
}

// ----------------------------------------------------------------------------
// launch
// ----------------------------------------------------------------------------
extern "C" void kernel_launch(void* const* d_in, const int* in_sizes, int n_in,
                              void* d_out, int out_size)
{
    // input index resolution (robust to presence/absence of scalar H, W)
    int ri = 1;
    while (ri < n_in && in_sizes[ri] != NN * NN) ri++;

    const float* x        = (const float*)d_in[0];
    const int*   relidx   = (const int*)d_in[ri];
    const float* table    = (const float*)d_in[ri + 1];
    const float* seqscale = (const float*)d_in[ri + 2];
    const float* qkv_w    = (const float*)d_in[ri + 3];
    const float* qkv_b    = (const float*)d_in[ri + 4];
    const float* proj_w   = (const float*)d_in[ri + 5];
    const float* proj_b   = (const float*)d_in[ri + 6];
    const float* temp     = (const float*)d_in[ri + 7];
    const float* qemb     = (const float*)d_in[ri + 8];
    const float* fc1w     = (const float*)d_in[ri + 9];
    const float* fc1b     = (const float*)d_in[ri + 10];
    const float* fc2w     = (const float*)d_in[ri + 11];
    const float* fc2b     = (const float*)d_in[ri + 12];
    float* out = (float*)d_out;

    float *qkvbuf = nullptr, *attnbuf = nullptr;
    cudaGetSymbolAddress((void**)&qkvbuf, g_qkv);
    cudaGetSymbolAddress((void**)&attnbuf, g_attn);

    // 1) QKV projection: (8192 x 1536) = x @ qkv_w^T + qkv_b
    {
        dim3 grid(3 * CC / 128, M_ROWS / 128);
        sgemm_bias_kernel<<<grid, 256>>>(x, qkv_w, qkv_b, qkvbuf,
                                         M_ROWS, 3 * CC, CC);
    }

    // 2) CPB MLP -> bias table (T, heads)
    cpb_kernel<<<T_ROWS, 512>>>(table, fc1w, fc1b, fc2w, fc2b);

    // 3) normalize/scale q,k and re-lay-out to (b,h,n,d)
    prep_kernel<<<M_ROWS * HEADS / 8, 256>>>(temp, qemb, seqscale);

    // 4) flash attention with bias gather
    {
        cudaFuncSetAttribute(attn_kernel,
                             cudaFuncAttributeMaxDynamicSharedMemorySize,
                             ATTN_SMEM);
        dim3 grid(BB * HEADS, NN / 64);
        attn_kernel<<<grid, 256, ATTN_SMEM>>>(relidx);
    }

    // 5) output projection: out = attn @ proj_w^T + proj_b
    {
        dim3 grid(CC / 128, M_ROWS / 128);
        sgemm_bias_kernel<<<grid, 256>>>(attnbuf, proj_w, proj_b, out,
                                         M_ROWS, CC, CC);
    }
}

// round 2
// speedup vs baseline: 1.1274x; 1.1274x over previous
#include <cuda_runtime.h>
#include <math.h>

// Problem constants
#define BB 8
#define NN 1024
#define CC 512
#define HEADS 8
#define HD 64
#define T_ROWS 3969
#define M_ROWS (BB * NN)      // 8192
#define CPB_HIDDEN 512

// ----------------------------------------------------------------------------
// Scratch (static device globals; no runtime allocation)
// ----------------------------------------------------------------------------
__device__ float g_qkv[(size_t)M_ROWS * 3 * CC];            // 8192 x 1536
__device__ float g_q[(size_t)BB * HEADS * NN * HD];          // normalized+scaled q
__device__ float g_k[(size_t)BB * HEADS * NN * HD];          // normalized k
__device__ float g_v[(size_t)BB * HEADS * NN * HD];          // v (re-laid-out)
__device__ float g_bias[T_ROWS * HEADS];                     // CPB table output
__device__ float g_attn[(size_t)M_ROWS * CC];                // attention output (b,n,h,d)

// ----------------------------------------------------------------------------
// SGEMM: C[M,N] = A[M,K] @ W[N,K]^T + bias[N]
// 128x128 block tile, BK=8, 256 threads, 8x8 per thread.
// ----------------------------------------------------------------------------
__global__ __launch_bounds__(256) void sgemm_bias_kernel(
    const float* __restrict__ A, const float* __restrict__ W,
    const float* __restrict__ bias, float* __restrict__ C,
    int M, int N, int K)
{
    __shared__ float sA[8][128];
    __shared__ float sB[8][128];

    int tid = threadIdx.x;
    int m0 = blockIdx.y * 128;
    int n0 = blockIdx.x * 128;
    int row0 = (tid >> 4) * 8;
    int col0 = (tid & 15) * 8;

    int lr = tid >> 1;
    int lk = (tid & 1) * 4;

    const float* Ap = A + (size_t)(m0 + lr) * K + lk;
    const float* Wp = W + (size_t)(n0 + lr) * K + lk;

    float acc[8][8];
#pragma unroll
    for (int i = 0; i < 8; i++)
#pragma unroll
        for (int j = 0; j < 8; j++) acc[i][j] = 0.f;

    for (int k0 = 0; k0 < K; k0 += 8) {
        float4 av = *(const float4*)(Ap + k0);
        float4 wv = *(const float4*)(Wp + k0);
        sA[lk + 0][lr] = av.x; sA[lk + 1][lr] = av.y;
        sA[lk + 2][lr] = av.z; sA[lk + 3][lr] = av.w;
        sB[lk + 0][lr] = wv.x; sB[lk + 1][lr] = wv.y;
        sB[lk + 2][lr] = wv.z; sB[lk + 3][lr] = wv.w;
        __syncthreads();
#pragma unroll
        for (int kk = 0; kk < 8; kk++) {
            float a[8], b[8];
#pragma unroll
            for (int i = 0; i < 8; i++) a[i] = sA[kk][row0 + i];
#pragma unroll
            for (int j = 0; j < 8; j++) b[j] = sB[kk][col0 + j];
#pragma unroll
            for (int i = 0; i < 8; i++)
#pragma unroll
                for (int j = 0; j < 8; j++) acc[i][j] += a[i] * b[j];
        }
        __syncthreads();
    }

#pragma unroll
    for (int i = 0; i < 8; i++) {
        size_t out_row = (size_t)(m0 + row0 + i) * N + n0 + col0;
#pragma unroll
        for (int j = 0; j < 8; j++)
            C[out_row + j] = acc[i][j] + bias[n0 + col0 + j];
    }
}

// ----------------------------------------------------------------------------
// CPB MLP
// ----------------------------------------------------------------------------
__global__ __launch_bounds__(512) void cpb_kernel(
    const float* __restrict__ table,
    const float* __restrict__ fc1w, const float* __restrict__ fc1b,
    const float* __restrict__ fc2w, const float* __restrict__ fc2b)
{
    __shared__ float sh[CPB_HIDDEN];
    __shared__ float part[16];
    int t = blockIdx.x;
    int tid = threadIdx.x;

    float c0 = table[t * 2 + 0];
    float c1 = table[t * 2 + 1];
    float hv = c0 * fc1w[tid * 2 + 0] + c1 * fc1w[tid * 2 + 1] + fc1b[tid];
    sh[tid] = fmaxf(hv, 0.f);
    __syncthreads();

    int w = tid >> 5, lane = tid & 31;
    int head = w & 7, seg = w >> 3;
    float s = 0.f;
#pragma unroll
    for (int i = 0; i < 8; i++) {
        int j = seg * 256 + i * 32 + lane;
        s += sh[j] * fc2w[head * CPB_HIDDEN + j];
    }
#pragma unroll
    for (int off = 16; off; off >>= 1)
        s += __shfl_xor_sync(0xffffffffu, s, off);
    if (lane == 0) part[w] = s;
    __syncthreads();
    if (tid < 8) g_bias[t * 8 + tid] = part[tid] + part[tid + 8] + fc2b[tid];
}

// ----------------------------------------------------------------------------
// Prep: split qkv per-(b,h); L2-normalize q,k; scale q.
// ----------------------------------------------------------------------------
__global__ __launch_bounds__(256) void prep_kernel(
    const float* __restrict__ temperature,
    const float* __restrict__ query_emb,
    const float* __restrict__ seq_scale)
{
    int gid = blockIdx.x * 8 + (threadIdx.x >> 5);
    int lane = threadIdx.x & 31;
    int m = gid >> 3, h = gid & 7;
    int b = m >> 10, n = m & 1023;

    const float* src = g_qkv + (size_t)m * (3 * CC) + h * HD;
    float q0 = src[lane],           q1 = src[lane + 32];
    float k0 = src[CC + lane],      k1 = src[CC + lane + 32];
    float v0 = src[2 * CC + lane],  v1 = src[2 * CC + lane + 32];

    float sq = q0 * q0 + q1 * q1;
    float sk = k0 * k0 + k1 * k1;
#pragma unroll
    for (int off = 16; off; off >>= 1) {
        sq += __shfl_xor_sync(0xffffffffu, sq, off);
        sk += __shfl_xor_sync(0xffffffffu, sk, off);
    }
    float qinv = 1.f / fmaxf(sqrtf(sq), 1e-12f);
    float kinv = 1.f / fmaxf(sqrtf(sk), 1e-12f);

    float tv = temperature[h];
    float sp = (tv > 20.f) ? tv : log1pf(expf(tv));
    float scale = sp * seq_scale[0];

    size_t dst = ((size_t)(b * 8 + h) * NN + n) * HD;
    g_q[dst + lane]      = (q0 * qinv + query_emb[h * HD + lane]) * scale;
    g_q[dst + lane + 32] = (q1 * qinv + query_emb[h * HD + lane + 32]) * scale;
    g_k[dst + lane]      = k0 * kinv;
    g_k[dst + lane + 32] = k1 * kinv;
    g_v[dst + lane]      = v0;
    g_v[dst + lane + 32] = v1;
}

// ----------------------------------------------------------------------------
// Flash attention, 128q x 128k tile, 256 threads, 8x8 score tile / 8x4 out tile.
// Row/col ownership strided by 16 for bank-friendly LDS.128.
// smem: sQ/sK/sV 128 x 68 floats, sS 128 x 144 floats = 178176 B.
// ----------------------------------------------------------------------------
#define KP 68
#define SP 144
#define ATTN_SMEM ((3 * 128 * KP + 128 * SP) * 4)

__global__ __launch_bounds__(256, 1) void attn_kernel(const int* __restrict__ relidx)
{
    extern __shared__ float sm[];
    float* sQ = sm;
    float* sK = sm + 128 * KP;
    float* sV = sm + 2 * 128 * KP;
    float* sS = sm + 3 * 128 * KP;

    int bh = blockIdx.x;          // 0..63
    int qt = blockIdx.y;          // 0..7
    int h = bh & 7;
    int b = bh >> 3;
    int tid = threadIdx.x;
    int rgrp = tid >> 4;          // 0..15: owns rows rgrp + 16*i
    int cgrp = tid & 15;          // 0..15: owns cols cgrp + 16*j
    int q0g = qt * 128;

    // load Q tile (128 x 64)
    const float* Qg = g_q + ((size_t)bh * NN + q0g) * HD;
#pragma unroll
    for (int it = 0; it < 8; it++) {
        int i = tid + it * 256;
        int row = i >> 4, col4 = (i & 15) << 2;
        float4 v = *(const float4*)(Qg + row * HD + col4);
        *(float4*)(sQ + row * KP + col4) = v;
    }

    float mrow[8], lrow[8], o[8][4];
#pragma unroll
    for (int i = 0; i < 8; i++) {
        mrow[i] = -1e30f; lrow[i] = 0.f;
#pragma unroll
        for (int c = 0; c < 4; c++) o[i][c] = 0.f;
    }

    for (int kt = 0; kt < 8; kt++) {
        __syncthreads();   // prior PV done with sV/sS (and Q store visible on iter 0)
        const float* Kg = g_k + ((size_t)bh * NN + kt * 128) * HD;
        const float* Vg = g_v + ((size_t)bh * NN + kt * 128) * HD;
#pragma unroll
        for (int it = 0; it < 8; it++) {
            int i = tid + it * 256;
            int row = i >> 4, col4 = (i & 15) << 2;
            float4 kv = *(const float4*)(Kg + row * HD + col4);
            float4 vv = *(const float4*)(Vg + row * HD + col4);
            *(float4*)(sK + row * KP + col4) = kv;
            *(float4*)(sV + row * KP + col4) = vv;
        }
        __syncthreads();

        // scores: 8x8 register tile, vectorized over d
        float s[8][8];
#pragma unroll
        for (int i = 0; i < 8; i++)
#pragma unroll
            for (int j = 0; j < 8; j++) s[i][j] = 0.f;

#pragma unroll 4
        for (int d4 = 0; d4 < HD; d4 += 4) {
            float4 a4[8], b4[8];
#pragma unroll
            for (int i = 0; i < 8; i++)
                a4[i] = *(const float4*)(sQ + (rgrp + 16 * i) * KP + d4);
#pragma unroll
            for (int j = 0; j < 8; j++)
                b4[j] = *(const float4*)(sK + (cgrp + 16 * j) * KP + d4);
#pragma unroll
            for (int i = 0; i < 8; i++)
#pragma unroll
                for (int j = 0; j < 8; j++) {
                    s[i][j] += a4[i].x * b4[j].x;
                    s[i][j] += a4[i].y * b4[j].y;
                    s[i][j] += a4[i].z * b4[j].z;
                    s[i][j] += a4[i].w * b4[j].w;
                }
        }

        // gathered relative-position bias
#pragma unroll
        for (int i = 0; i < 8; i++) {
            const int* ip = relidx + (size_t)(q0g + rgrp + 16 * i) * NN + kt * 128 + cgrp;
#pragma unroll
            for (int j = 0; j < 8; j++)
                s[i][j] += g_bias[ip[16 * j] * 8 + h];
        }

        // online softmax per row (16 lanes share a row set)
#pragma unroll
        for (int i = 0; i < 8; i++) {
            float mt = s[i][0];
#pragma unroll
            for (int j = 1; j < 8; j++) mt = fmaxf(mt, s[i][j]);
#pragma unroll
            for (int off = 8; off; off >>= 1)
                mt = fmaxf(mt, __shfl_xor_sync(0xffffffffu, mt, off, 16));
            float nm = fmaxf(mrow[i], mt);
            float corr = __expf(mrow[i] - nm);
            float ps = 0.f;
#pragma unroll
            for (int j = 0; j < 8; j++) {
                s[i][j] = __expf(s[i][j] - nm);
                ps += s[i][j];
            }
#pragma unroll
            for (int off = 8; off; off >>= 1)
                ps += __shfl_xor_sync(0xffffffffu, ps, off, 16);
            lrow[i] = lrow[i] * corr + ps;
            mrow[i] = nm;
#pragma unroll
            for (int c = 0; c < 4; c++) o[i][c] *= corr;
#pragma unroll
            for (int j = 0; j < 8; j++)
                sS[(rgrp + 16 * i) * SP + cgrp + 16 * j] = s[i][j];
        }
        __syncthreads();

        // PV: o[8 rows][4 dims] += P[rows][128] @ V[128][dims], vectorized over k
#pragma unroll 4
        for (int k4 = 0; k4 < 128; k4 += 4) {
            float4 p4[8];
#pragma unroll
            for (int i = 0; i < 8; i++)
                p4[i] = *(const float4*)(sS + (rgrp + 16 * i) * SP + k4);
            float4 v4[4];
#pragma unroll
            for (int kk = 0; kk < 4; kk++)
                v4[kk] = *(const float4*)(sV + (k4 + kk) * KP + cgrp * 4);
#pragma unroll
            for (int i = 0; i < 8; i++) {
                o[i][0] += p4[i].x * v4[0].x + p4[i].y * v4[1].x
                         + p4[i].z * v4[2].x + p4[i].w * v4[3].x;
                o[i][1] += p4[i].x * v4[0].y + p4[i].y * v4[1].y
                         + p4[i].z * v4[2].y + p4[i].w * v4[3].y;
                o[i][2] += p4[i].x * v4[0].z + p4[i].y * v4[1].z
                         + p4[i].z * v4[2].z + p4[i].w * v4[3].z;
                o[i][3] += p4[i].x * v4[0].w + p4[i].y * v4[1].w
                         + p4[i].z * v4[2].w + p4[i].w * v4[3].w;
            }
        }
    }

    // epilogue: normalize by denom, write (b,n,h,d) layout (float4)
#pragma unroll
    for (int i = 0; i < 8; i++) {
        float inv = 1.f / lrow[i];
        int row = q0g + rgrp + 16 * i;
        float4 ov;
        ov.x = o[i][0] * inv; ov.y = o[i][1] * inv;
        ov.z = o[i][2] * inv; ov.w = o[i][3] * inv;
        *(float4*)(g_attn + ((size_t)b * NN + row) * CC + h * HD + cgrp * 4) = ov;
    }
}

// ----------------------------------------------------------------------------
// launch
// ----------------------------------------------------------------------------
extern "C" void kernel_launch(void* const* d_in, const int* in_sizes, int n_in,
                              void* d_out, int out_size)
{
    int ri = 1;
    while (ri < n_in && in_sizes[ri] != NN * NN) ri++;

    const float* x        = (const float*)d_in[0];
    const int*   relidx   = (const int*)d_in[ri];
    const float* table    = (const float*)d_in[ri + 1];
    const float* seqscale = (const float*)d_in[ri + 2];
    const float* qkv_w    = (const float*)d_in[ri + 3];
    const float* qkv_b    = (const float*)d_in[ri + 4];
    const float* proj_w   = (const float*)d_in[ri + 5];
    const float* proj_b   = (const float*)d_in[ri + 6];
    const float* temp     = (const float*)d_in[ri + 7];
    const float* qemb     = (const float*)d_in[ri + 8];
    const float* fc1w     = (const float*)d_in[ri + 9];
    const float* fc1b     = (const float*)d_in[ri + 10];
    const float* fc2w     = (const float*)d_in[ri + 11];
    const float* fc2b     = (const float*)d_in[ri + 12];
    float* out = (float*)d_out;

    float *qkvbuf = nullptr, *attnbuf = nullptr;
    cudaGetSymbolAddress((void**)&qkvbuf, g_qkv);
    cudaGetSymbolAddress((void**)&attnbuf, g_attn);

    // 1) QKV projection
    {
        dim3 grid(3 * CC / 128, M_ROWS / 128);
        sgemm_bias_kernel<<<grid, 256>>>(x, qkv_w, qkv_b, qkvbuf,
                                         M_ROWS, 3 * CC, CC);
    }

    // 2) CPB MLP -> bias table
    cpb_kernel<<<T_ROWS, 512>>>(table, fc1w, fc1b, fc2w, fc2b);

    // 3) normalize/scale and re-layout
    prep_kernel<<<M_ROWS * HEADS / 8, 256>>>(temp, qemb, seqscale);

    // 4) flash attention
    {
        cudaFuncSetAttribute(attn_kernel,
                             cudaFuncAttributeMaxDynamicSharedMemorySize,
                             ATTN_SMEM);
        dim3 grid(BB * HEADS, NN / 128);
        attn_kernel<<<grid, 256, ATTN_SMEM>>>(relidx);
    }

    // 5) output projection
    {
        dim3 grid(CC / 128, M_ROWS / 128);
        sgemm_bias_kernel<<<grid, 256>>>(attnbuf, proj_w, proj_b, out,
                                         M_ROWS, CC, CC);
    }
}

// round 3
// speedup vs baseline: 1.3150x; 1.1665x over previous
#include <cuda_runtime.h>
#include <math.h>

// Problem constants
#define BB 8
#define NN 1024
#define CC 512
#define HEADS 8
#define HD 64
#define T_ROWS 3969
#define M_ROWS (BB * NN)      // 8192
#define CPB_HIDDEN 512

// ----------------------------------------------------------------------------
// Scratch (static device globals; no runtime allocation)
// ----------------------------------------------------------------------------
__device__ float g_qkv[(size_t)M_ROWS * 3 * CC];
__device__ float g_q[(size_t)BB * HEADS * NN * HD];
__device__ float g_k[(size_t)BB * HEADS * NN * HD];
__device__ float g_v[(size_t)BB * HEADS * NN * HD];
__device__ float g_bias[T_ROWS * HEADS];
__device__ float g_biasmat[(size_t)HEADS * NN * NN];   // materialized (h, n, m)
__device__ float g_attn[(size_t)M_ROWS * CC];

// ----------------------------------------------------------------------------
// SGEMM: C[M,N] = A[M,K] @ W[N,K]^T + bias[N]
// ----------------------------------------------------------------------------
__global__ __launch_bounds__(256) void sgemm_bias_kernel(
    const float* __restrict__ A, const float* __restrict__ W,
    const float* __restrict__ bias, float* __restrict__ C,
    int M, int N, int K)
{
    __shared__ float sA[8][128];
    __shared__ float sB[8][128];

    int tid = threadIdx.x;
    int m0 = blockIdx.y * 128;
    int n0 = blockIdx.x * 128;
    int row0 = (tid >> 4) * 8;
    int col0 = (tid & 15) * 8;

    int lr = tid >> 1;
    int lk = (tid & 1) * 4;

    const float* Ap = A + (size_t)(m0 + lr) * K + lk;
    const float* Wp = W + (size_t)(n0 + lr) * K + lk;

    float acc[8][8];
#pragma unroll
    for (int i = 0; i < 8; i++)
#pragma unroll
        for (int j = 0; j < 8; j++) acc[i][j] = 0.f;

    for (int k0 = 0; k0 < K; k0 += 8) {
        float4 av = *(const float4*)(Ap + k0);
        float4 wv = *(const float4*)(Wp + k0);
        sA[lk + 0][lr] = av.x; sA[lk + 1][lr] = av.y;
        sA[lk + 2][lr] = av.z; sA[lk + 3][lr] = av.w;
        sB[lk + 0][lr] = wv.x; sB[lk + 1][lr] = wv.y;
        sB[lk + 2][lr] = wv.z; sB[lk + 3][lr] = wv.w;
        __syncthreads();
#pragma unroll
        for (int kk = 0; kk < 8; kk++) {
            float a[8], b[8];
#pragma unroll
            for (int i = 0; i < 8; i++) a[i] = sA[kk][row0 + i];
#pragma unroll
            for (int j = 0; j < 8; j++) b[j] = sB[kk][col0 + j];
#pragma unroll
            for (int i = 0; i < 8; i++)
#pragma unroll
                for (int j = 0; j < 8; j++) acc[i][j] += a[i] * b[j];
        }
        __syncthreads();
    }

#pragma unroll
    for (int i = 0; i < 8; i++) {
        size_t out_row = (size_t)(m0 + row0 + i) * N + n0 + col0;
#pragma unroll
        for (int j = 0; j < 8; j++)
            C[out_row + j] = acc[i][j] + bias[n0 + col0 + j];
    }
}

// ----------------------------------------------------------------------------
// CPB MLP
// ----------------------------------------------------------------------------
__global__ __launch_bounds__(512) void cpb_kernel(
    const float* __restrict__ table,
    const float* __restrict__ fc1w, const float* __restrict__ fc1b,
    const float* __restrict__ fc2w, const float* __restrict__ fc2b)
{
    __shared__ float sh[CPB_HIDDEN];
    __shared__ float part[16];
    int t = blockIdx.x;
    int tid = threadIdx.x;

    float c0 = table[t * 2 + 0];
    float c1 = table[t * 2 + 1];
    float hv = c0 * fc1w[tid * 2 + 0] + c1 * fc1w[tid * 2 + 1] + fc1b[tid];
    sh[tid] = fmaxf(hv, 0.f);
    __syncthreads();

    int w = tid >> 5, lane = tid & 31;
    int head = w & 7, seg = w >> 3;
    float s = 0.f;
#pragma unroll
    for (int i = 0; i < 8; i++) {
        int j = seg * 256 + i * 32 + lane;
        s += sh[j] * fc2w[head * CPB_HIDDEN + j];
    }
#pragma unroll
    for (int off = 16; off; off >>= 1)
        s += __shfl_xor_sync(0xffffffffu, s, off);
    if (lane == 0) part[w] = s;
    __syncthreads();
    if (tid < 8) g_bias[t * 8 + tid] = part[tid] + part[tid + 8] + fc2b[tid];
}

// ----------------------------------------------------------------------------
// Materialize bias matrix: biasmat[h][n][m] = bias_tab[relidx[n][m]][h].
// One thread per (h, n, m4). 127KB table stays L1/L2 resident.
// ----------------------------------------------------------------------------
__global__ __launch_bounds__(256) void bias_mat_kernel(const int* __restrict__ relidx)
{
    int gid = blockIdx.x * 256 + threadIdx.x;   // 0 .. 8*1024*256-1
    int m4 = gid & 255;
    int n  = (gid >> 8) & 1023;
    int h  = gid >> 18;
    int4 idx = *(const int4*)(relidx + (size_t)n * NN + m4 * 4);
    float4 o;
    o.x = g_bias[idx.x * 8 + h];
    o.y = g_bias[idx.y * 8 + h];
    o.z = g_bias[idx.z * 8 + h];
    o.w = g_bias[idx.w * 8 + h];
    *(float4*)(g_biasmat + ((size_t)h * NN + n) * NN + m4 * 4) = o;
}

// ----------------------------------------------------------------------------
// Prep: split qkv per-(b,h); L2-normalize q,k; scale q.
// ----------------------------------------------------------------------------
__global__ __launch_bounds__(256) void prep_kernel(
    const float* __restrict__ temperature,
    const float* __restrict__ query_emb,
    const float* __restrict__ seq_scale)
{
    int gid = blockIdx.x * 8 + (threadIdx.x >> 5);
    int lane = threadIdx.x & 31;
    int m = gid >> 3, h = gid & 7;
    int b = m >> 10, n = m & 1023;

    const float* src = g_qkv + (size_t)m * (3 * CC) + h * HD;
    float q0 = src[lane],           q1 = src[lane + 32];
    float k0 = src[CC + lane],      k1 = src[CC + lane + 32];
    float v0 = src[2 * CC + lane],  v1 = src[2 * CC + lane + 32];

    float sq = q0 * q0 + q1 * q1;
    float sk = k0 * k0 + k1 * k1;
#pragma unroll
    for (int off = 16; off; off >>= 1) {
        sq += __shfl_xor_sync(0xffffffffu, sq, off);
        sk += __shfl_xor_sync(0xffffffffu, sk, off);
    }
    float qinv = 1.f / fmaxf(sqrtf(sq), 1e-12f);
    float kinv = 1.f / fmaxf(sqrtf(sk), 1e-12f);

    float tv = temperature[h];
    float sp = (tv > 20.f) ? tv : log1pf(expf(tv));
    float scale = sp * seq_scale[0];

    size_t dst = ((size_t)(b * 8 + h) * NN + n) * HD;
    g_q[dst + lane]      = (q0 * qinv + query_emb[h * HD + lane]) * scale;
    g_q[dst + lane + 32] = (q1 * qinv + query_emb[h * HD + lane + 32]) * scale;
    g_k[dst + lane]      = k0 * kinv;
    g_k[dst + lane + 32] = k1 * kinv;
    g_v[dst + lane]      = v0;
    g_v[dst + lane + 32] = v1;
}

// ----------------------------------------------------------------------------
// Flash attention, 128q x 128k tile, 512 threads (16 warps), 4x8 score tile.
// Rows owned: rgrp + 32*i (rgrp=tid>>4, i<4). Cols: cgrp + 16*j (cgrp=tid&15).
// Bias read linearly from materialized g_biasmat (L2-hot, shared across b).
// ----------------------------------------------------------------------------
#define KP 68
#define SP 144
#define ATTN_SMEM ((3 * 128 * KP + 128 * SP) * 4)

__global__ __launch_bounds__(512, 1) void attn_kernel()
{
    extern __shared__ float sm[];
    float* sQ = sm;
    float* sK = sm + 128 * KP;
    float* sV = sm + 2 * 128 * KP;
    float* sS = sm + 3 * 128 * KP;

    int bh = blockIdx.x;          // 0..63
    int qt = blockIdx.y;          // 0..7
    int h = bh & 7;
    int b = bh >> 3;
    int tid = threadIdx.x;
    int rgrp = tid >> 4;          // 0..31
    int cgrp = tid & 15;          // 0..15
    int q0g = qt * 128;

    // load Q tile (128 x 64): 2048 float4 / 512 threads = 4 iters
    const float* Qg = g_q + ((size_t)bh * NN + q0g) * HD;
#pragma unroll
    for (int it = 0; it < 4; it++) {
        int i = tid + it * 512;
        int row = i >> 4, col4 = (i & 15) << 2;
        *(float4*)(sQ + row * KP + col4) = *(const float4*)(Qg + row * HD + col4);
    }

    float mrow[4], lrow[4], o[4][4];
#pragma unroll
    for (int i = 0; i < 4; i++) {
        mrow[i] = -1e30f; lrow[i] = 0.f;
#pragma unroll
        for (int c = 0; c < 4; c++) o[i][c] = 0.f;
    }

    const float* bmat = g_biasmat + ((size_t)h * NN + q0g) * NN;

    for (int kt = 0; kt < 8; kt++) {
        __syncthreads();
        const float* Kg = g_k + ((size_t)bh * NN + kt * 128) * HD;
        const float* Vg = g_v + ((size_t)bh * NN + kt * 128) * HD;
#pragma unroll
        for (int it = 0; it < 4; it++) {
            int i = tid + it * 512;
            int row = i >> 4, col4 = (i & 15) << 2;
            *(float4*)(sK + row * KP + col4) = *(const float4*)(Kg + row * HD + col4);
            *(float4*)(sV + row * KP + col4) = *(const float4*)(Vg + row * HD + col4);
        }
        __syncthreads();

        // scores: 4x8 register tile
        float s[4][8];
#pragma unroll
        for (int i = 0; i < 4; i++)
#pragma unroll
            for (int j = 0; j < 8; j++) s[i][j] = 0.f;

#pragma unroll 4
        for (int d4 = 0; d4 < HD; d4 += 4) {
            float4 a4[4], b4[8];
#pragma unroll
            for (int i = 0; i < 4; i++)
                a4[i] = *(const float4*)(sQ + (rgrp + 32 * i) * KP + d4);
#pragma unroll
            for (int j = 0; j < 8; j++)
                b4[j] = *(const float4*)(sK + (cgrp + 16 * j) * KP + d4);
#pragma unroll
            for (int i = 0; i < 4; i++)
#pragma unroll
                for (int j = 0; j < 8; j++) {
                    s[i][j] += a4[i].x * b4[j].x;
                    s[i][j] += a4[i].y * b4[j].y;
                    s[i][j] += a4[i].z * b4[j].z;
                    s[i][j] += a4[i].w * b4[j].w;
                }
        }

        // materialized bias (linear, L2-hot)
#pragma unroll
        for (int i = 0; i < 4; i++) {
            const float* bp = bmat + (size_t)(rgrp + 32 * i) * NN + kt * 128 + cgrp;
#pragma unroll
            for (int j = 0; j < 8; j++)
                s[i][j] += __ldg(bp + 16 * j);
        }

        // online softmax (16-lane row groups)
#pragma unroll
        for (int i = 0; i < 4; i++) {
            float mt = s[i][0];
#pragma unroll
            for (int j = 1; j < 8; j++) mt = fmaxf(mt, s[i][j]);
#pragma unroll
            for (int off = 8; off; off >>= 1)
                mt = fmaxf(mt, __shfl_xor_sync(0xffffffffu, mt, off, 16));
            float nm = fmaxf(mrow[i], mt);
            float corr = __expf(mrow[i] - nm);
            float ps = 0.f;
#pragma unroll
            for (int j = 0; j < 8; j++) {
                s[i][j] = __expf(s[i][j] - nm);
                ps += s[i][j];
            }
#pragma unroll
            for (int off = 8; off; off >>= 1)
                ps += __shfl_xor_sync(0xffffffffu, ps, off, 16);
            lrow[i] = lrow[i] * corr + ps;
            mrow[i] = nm;
#pragma unroll
            for (int c = 0; c < 4; c++) o[i][c] *= corr;
#pragma unroll
            for (int j = 0; j < 8; j++)
                sS[(rgrp + 32 * i) * SP + cgrp + 16 * j] = s[i][j];
        }
        __syncthreads();

        // PV: o[4 rows][4 dims] += P[rows][128] @ V[128][dims]
#pragma unroll 4
        for (int k4 = 0; k4 < 128; k4 += 4) {
            float4 p4[4];
#pragma unroll
            for (int i = 0; i < 4; i++)
                p4[i] = *(const float4*)(sS + (rgrp + 32 * i) * SP + k4);
            float4 v4[4];
#pragma unroll
            for (int kk = 0; kk < 4; kk++)
                v4[kk] = *(const float4*)(sV + (k4 + kk) * KP + cgrp * 4);
#pragma unroll
            for (int i = 0; i < 4; i++) {
                o[i][0] += p4[i].x * v4[0].x + p4[i].y * v4[1].x
                         + p4[i].z * v4[2].x + p4[i].w * v4[3].x;
                o[i][1] += p4[i].x * v4[0].y + p4[i].y * v4[1].y
                         + p4[i].z * v4[2].y + p4[i].w * v4[3].y;
                o[i][2] += p4[i].x * v4[0].z + p4[i].y * v4[1].z
                         + p4[i].z * v4[2].z + p4[i].w * v4[3].z;
                o[i][3] += p4[i].x * v4[0].w + p4[i].y * v4[1].w
                         + p4[i].z * v4[2].w + p4[i].w * v4[3].w;
            }
        }
    }

    // epilogue
#pragma unroll
    for (int i = 0; i < 4; i++) {
        float inv = 1.f / lrow[i];
        int row = q0g + rgrp + 32 * i;
        float4 ov;
        ov.x = o[i][0] * inv; ov.y = o[i][1] * inv;
        ov.z = o[i][2] * inv; ov.w = o[i][3] * inv;
        *(float4*)(g_attn + ((size_t)b * NN + row) * CC + h * HD + cgrp * 4) = ov;
    }
}

// ----------------------------------------------------------------------------
// launch
// ----------------------------------------------------------------------------
extern "C" void kernel_launch(void* const* d_in, const int* in_sizes, int n_in,
                              void* d_out, int out_size)
{
    int ri = 1;
    while (ri < n_in && in_sizes[ri] != NN * NN) ri++;

    const float* x        = (const float*)d_in[0];
    const int*   relidx   = (const int*)d_in[ri];
    const float* table    = (const float*)d_in[ri + 1];
    const float* seqscale = (const float*)d_in[ri + 2];
    const float* qkv_w    = (const float*)d_in[ri + 3];
    const float* qkv_b    = (const float*)d_in[ri + 4];
    const float* proj_w   = (const float*)d_in[ri + 5];
    const float* proj_b   = (const float*)d_in[ri + 6];
    const float* temp     = (const float*)d_in[ri + 7];
    const float* qemb     = (const float*)d_in[ri + 8];
    const float* fc1w     = (const float*)d_in[ri + 9];
    const float* fc1b     = (const float*)d_in[ri + 10];
    const float* fc2w     = (const float*)d_in[ri + 11];
    const float* fc2b     = (const float*)d_in[ri + 12];
    float* out = (float*)d_out;

    float *qkvbuf = nullptr, *attnbuf = nullptr;
    cudaGetSymbolAddress((void**)&qkvbuf, g_qkv);
    cudaGetSymbolAddress((void**)&attnbuf, g_attn);

    // 1) QKV projection
    {
        dim3 grid(3 * CC / 128, M_ROWS / 128);
        sgemm_bias_kernel<<<grid, 256>>>(x, qkv_w, qkv_b, qkvbuf,
                                         M_ROWS, 3 * CC, CC);
    }

    // 2) CPB MLP -> bias table, then materialize full bias matrix
    cpb_kernel<<<T_ROWS, 512>>>(table, fc1w, fc1b, fc2w, fc2b);
    bias_mat_kernel<<<HEADS * NN * (NN / 4) / 256, 256>>>(relidx);

    // 3) normalize/scale and re-layout
    prep_kernel<<<M_ROWS * HEADS / 8, 256>>>(temp, qemb, seqscale);

    // 4) flash attention
    {
        cudaFuncSetAttribute(attn_kernel,
                             cudaFuncAttributeMaxDynamicSharedMemorySize,
                             ATTN_SMEM);
        dim3 grid(BB * HEADS, NN / 128);
        attn_kernel<<<grid, 512, ATTN_SMEM>>>();
    }

    // 5) output projection
    {
        dim3 grid(CC / 128, M_ROWS / 128);
        sgemm_bias_kernel<<<grid, 256>>>(attnbuf, proj_w, proj_b, out,
                                         M_ROWS, CC, CC);
    }
}

// round 5
// speedup vs baseline: 1.5233x; 1.1584x over previous
#include <cuda_runtime.h>
#include <math.h>
#include <stdint.h>

// Problem constants
#define BB 8
#define NN 1024
#define CC 512
#define HEADS 8
#define HD 64
#define T_ROWS 3969
#define M_ROWS (BB * NN)      // 8192
#define CPB_HIDDEN 512

// ----------------------------------------------------------------------------
// Scratch (static device globals; no runtime allocation)
// ----------------------------------------------------------------------------
__device__ float g_qkv[(size_t)M_ROWS * 3 * CC];
__device__ float g_q[(size_t)BB * HEADS * NN * HD];
__device__ float g_k[(size_t)BB * HEADS * NN * HD];
__device__ float g_v[(size_t)BB * HEADS * NN * HD];
__device__ float g_bias[T_ROWS * HEADS];
__device__ float g_biasmat[(size_t)HEADS * NN * NN];
__device__ float g_attn[(size_t)M_ROWS * CC];
// tf32 split buffers
__device__ float g_ahi[(size_t)M_ROWS * CC];
__device__ float g_alo[(size_t)M_ROWS * CC];
__device__ float g_whi[(size_t)3 * CC * CC];
__device__ float g_wlo[(size_t)3 * CC * CC];

// ----------------------------------------------------------------------------
// tf32 helpers
// ----------------------------------------------------------------------------
__device__ __forceinline__ float tf32_rna(float v) {
    uint32_t r;
    asm("cvt.rna.tf32.f32 %0, %1;" : "=r"(r) : "f"(v));
    return __uint_as_float(r);
}

__device__ __forceinline__ void mma_tf32(float* d, uint32_t a0, uint32_t a1,
                                         uint32_t a2, uint32_t a3,
                                         uint32_t b0, uint32_t b1) {
    asm volatile(
        "mma.sync.aligned.m16n8k8.row.col.f32.tf32.tf32.f32 "
        "{%0,%1,%2,%3}, {%4,%5,%6,%7}, {%8,%9}, {%0,%1,%2,%3};"
        : "+f"(d[0]), "+f"(d[1]), "+f"(d[2]), "+f"(d[3])
        : "r"(a0), "r"(a1), "r"(a2), "r"(a3), "r"(b0), "r"(b1));
}

// ----------------------------------------------------------------------------
// Split a float array into tf32 hi/lo parts (float4 elementwise)
// ----------------------------------------------------------------------------
__global__ __launch_bounds__(256) void split_kernel(
    const float* __restrict__ src, float* __restrict__ hi,
    float* __restrict__ lo, int n4)
{
    int i = blockIdx.x * 256 + threadIdx.x;
    if (i >= n4) return;
    float4 v = *(const float4*)(src + i * 4);
    float4 h, l;
    h.x = tf32_rna(v.x); l.x = tf32_rna(v.x - h.x);
    h.y = tf32_rna(v.y); l.y = tf32_rna(v.y - h.y);
    h.z = tf32_rna(v.z); l.z = tf32_rna(v.z - h.z);
    h.w = tf32_rna(v.w); l.w = tf32_rna(v.w - h.w);
    *(float4*)(hi + i * 4) = h;
    *(float4*)(lo + i * 4) = l;
}

// ----------------------------------------------------------------------------
// tf32 mma GEMM (3x split): C[M,Nn] = A[M,512] @ W[Nn,512]^T + bias[Nn]
// CTA 128x128, BK=32, 8 warps of 32x64 (2 m16-frags x 8 n8-frags).
// smem rows padded to 36 words -> conflict-free fragment loads.
// ----------------------------------------------------------------------------
#define GP 36
#define GEMM_SMEM (4 * 128 * GP * 4)   // Ahi, Alo, Bhi, Blo

__global__ __launch_bounds__(256, 1)
void mma_gemm_kernel(const float* __restrict__ Ahi, const float* __restrict__ Alo,
                     const float* __restrict__ Bhi, const float* __restrict__ Blo,
                     const float* __restrict__ bias, float* __restrict__ C, int Nn)
{
    extern __shared__ float sm[];
    float* sAh = sm;
    float* sAl = sm + 128 * GP;
    float* sBh = sm + 2 * 128 * GP;
    float* sBl = sm + 3 * 128 * GP;

    int tid = threadIdx.x;
    int wid = tid >> 5, lane = tid & 31;
    int g = lane >> 2, t = lane & 3;
    int wm = (wid & 3) * 32;       // warp m offset in tile
    int wn = (wid >> 2) * 64;      // warp n offset in tile
    int m0 = blockIdx.y * 128, n0 = blockIdx.x * 128;

    float d[2][8][4];
#pragma unroll
    for (int mt = 0; mt < 2; mt++)
#pragma unroll
        for (int nt = 0; nt < 8; nt++)
#pragma unroll
            for (int r = 0; r < 4; r++) d[mt][nt][r] = 0.f;

    for (int ch = 0; ch < 16; ch++) {
        __syncthreads();
#pragma unroll
        for (int it = 0; it < 4; it++) {
            int idx = tid + it * 256;
            int m = idx >> 3, k4 = (idx & 7) << 2;
            size_t goff = (size_t)(m0 + m) * 512 + ch * 32 + k4;
            size_t boff = (size_t)(n0 + m) * 512 + ch * 32 + k4;
            *(float4*)(sAh + m * GP + k4) = *(const float4*)(Ahi + goff);
            *(float4*)(sAl + m * GP + k4) = *(const float4*)(Alo + goff);
            *(float4*)(sBh + m * GP + k4) = *(const float4*)(Bhi + boff);
            *(float4*)(sBl + m * GP + k4) = *(const float4*)(Blo + boff);
        }
        __syncthreads();

#pragma unroll
        for (int ks = 0; ks < 4; ks++) {
            uint32_t ah[2][4], al[2][4];
#pragma unroll
            for (int mt = 0; mt < 2; mt++) {
                const float* p = sAh + (wm + mt * 16 + g) * GP + ks * 8 + t;
                const float* q = sAl + (wm + mt * 16 + g) * GP + ks * 8 + t;
                ah[mt][0] = __float_as_uint(p[0]);
                ah[mt][1] = __float_as_uint(p[8 * GP]);
                ah[mt][2] = __float_as_uint(p[4]);
                ah[mt][3] = __float_as_uint(p[8 * GP + 4]);
                al[mt][0] = __float_as_uint(q[0]);
                al[mt][1] = __float_as_uint(q[8 * GP]);
                al[mt][2] = __float_as_uint(q[4]);
                al[mt][3] = __float_as_uint(q[8 * GP + 4]);
            }
            uint32_t bh[8][2], bl[8][2];
#pragma unroll
            for (int nt = 0; nt < 8; nt++) {
                const float* p = sBh + (wn + nt * 8 + g) * GP + ks * 8 + t;
                const float* q = sBl + (wn + nt * 8 + g) * GP + ks * 8 + t;
                bh[nt][0] = __float_as_uint(p[0]);
                bh[nt][1] = __float_as_uint(p[4]);
                bl[nt][0] = __float_as_uint(q[0]);
                bl[nt][1] = __float_as_uint(q[4]);
            }
#pragma unroll
            for (int mt = 0; mt < 2; mt++)
#pragma unroll
                for (int nt = 0; nt < 8; nt++) {
                    mma_tf32(d[mt][nt], ah[mt][0], ah[mt][1], ah[mt][2], ah[mt][3],
                             bh[nt][0], bh[nt][1]);
                    mma_tf32(d[mt][nt], ah[mt][0], ah[mt][1], ah[mt][2], ah[mt][3],
                             bl[nt][0], bl[nt][1]);
                    mma_tf32(d[mt][nt], al[mt][0], al[mt][1], al[mt][2], al[mt][3],
                             bh[nt][0], bh[nt][1]);
                }
        }
    }

    // epilogue: add bias, write float2 pairs
#pragma unroll
    for (int nt = 0; nt < 8; nt++) {
        int col = n0 + wn + nt * 8 + 2 * t;
        float b0 = bias[col], b1 = bias[col + 1];
#pragma unroll
        for (int mt = 0; mt < 2; mt++) {
            int row = m0 + wm + mt * 16 + g;
            float2 v0 = make_float2(d[mt][nt][0] + b0, d[mt][nt][1] + b1);
            float2 v1 = make_float2(d[mt][nt][2] + b0, d[mt][nt][3] + b1);
            *(float2*)(C + (size_t)row * Nn + col) = v0;
            *(float2*)(C + (size_t)(row + 8) * Nn + col) = v1;
        }
    }
}

// ----------------------------------------------------------------------------
// CPB MLP
// ----------------------------------------------------------------------------
__global__ __launch_bounds__(512) void cpb_kernel(
    const float* __restrict__ table,
    const float* __restrict__ fc1w, const float* __restrict__ fc1b,
    const float* __restrict__ fc2w, const float* __restrict__ fc2b)
{
    __shared__ float sh[CPB_HIDDEN];
    __shared__ float part[16];
    int t = blockIdx.x;
    int tid = threadIdx.x;

    float c0 = table[t * 2 + 0];
    float c1 = table[t * 2 + 1];
    float hv = c0 * fc1w[tid * 2 + 0] + c1 * fc1w[tid * 2 + 1] + fc1b[tid];
    sh[tid] = fmaxf(hv, 0.f);
    __syncthreads();

    int w = tid >> 5, lane = tid & 31;
    int head = w & 7, seg = w >> 3;
    float s = 0.f;
#pragma unroll
    for (int i = 0; i < 8; i++) {
        int j = seg * 256 + i * 32 + lane;
        s += sh[j] * fc2w[head * CPB_HIDDEN + j];
    }
#pragma unroll
    for (int off = 16; off; off >>= 1)
        s += __shfl_xor_sync(0xffffffffu, s, off);
    if (lane == 0) part[w] = s;
    __syncthreads();
    if (tid < 8) g_bias[t * 8 + tid] = part[tid] + part[tid + 8] + fc2b[tid];
}

// ----------------------------------------------------------------------------
// Materialize bias matrix
// ----------------------------------------------------------------------------
__global__ __launch_bounds__(256) void bias_mat_kernel(const int* __restrict__ relidx)
{
    int gid = blockIdx.x * 256 + threadIdx.x;
    int m4 = gid & 255;
    int n  = (gid >> 8) & 1023;
    int h  = gid >> 18;
    int4 idx = *(const int4*)(relidx + (size_t)n * NN + m4 * 4);
    float4 o;
    o.x = g_bias[idx.x * 8 + h];
    o.y = g_bias[idx.y * 8 + h];
    o.z = g_bias[idx.z * 8 + h];
    o.w = g_bias[idx.w * 8 + h];
    *(float4*)(g_biasmat + ((size_t)h * NN + n) * NN + m4 * 4) = o;
}

// ----------------------------------------------------------------------------
// Prep: split qkv per-(b,h); L2-normalize q,k; scale q.
// ----------------------------------------------------------------------------
__global__ __launch_bounds__(256) void prep_kernel(
    const float* __restrict__ temperature,
    const float* __restrict__ query_emb,
    const float* __restrict__ seq_scale)
{
    int gid = blockIdx.x * 8 + (threadIdx.x >> 5);
    int lane = threadIdx.x & 31;
    int m = gid >> 3, h = gid & 7;
    int b = m >> 10, n = m & 1023;

    const float* src = g_qkv + (size_t)m * (3 * CC) + h * HD;
    float q0 = src[lane],           q1 = src[lane + 32];
    float k0 = src[CC + lane],      k1 = src[CC + lane + 32];
    float v0 = src[2 * CC + lane],  v1 = src[2 * CC + lane + 32];

    float sq = q0 * q0 + q1 * q1;
    float sk = k0 * k0 + k1 * k1;
#pragma unroll
    for (int off = 16; off; off >>= 1) {
        sq += __shfl_xor_sync(0xffffffffu, sq, off);
        sk += __shfl_xor_sync(0xffffffffu, sk, off);
    }
    float qinv = 1.f / fmaxf(sqrtf(sq), 1e-12f);
    float kinv = 1.f / fmaxf(sqrtf(sk), 1e-12f);

    float tv = temperature[h];
    float sp = (tv > 20.f) ? tv : log1pf(expf(tv));
    float scale = sp * seq_scale[0];

    size_t dst = ((size_t)(b * 8 + h) * NN + n) * HD;
    g_q[dst + lane]      = (q0 * qinv + query_emb[h * HD + lane]) * scale;
    g_q[dst + lane + 32] = (q1 * qinv + query_emb[h * HD + lane + 32]) * scale;
    g_k[dst + lane]      = k0 * kinv;
    g_k[dst + lane + 32] = k1 * kinv;
    g_v[dst + lane]      = v0;
    g_v[dst + lane + 32] = v1;
}

// ----------------------------------------------------------------------------
// Flash attention (fp32): 128x128 tile, 512 threads (unchanged, R3)
// ----------------------------------------------------------------------------
#define KP 68
#define SP 144
#define ATTN_SMEM ((3 * 128 * KP + 128 * SP) * 4)

__global__ __launch_bounds__(512, 1) void attn_kernel()
{
    extern __shared__ float sm[];
    float* sQ = sm;
    float* sK = sm + 128 * KP;
    float* sV = sm + 2 * 128 * KP;
    float* sS = sm + 3 * 128 * KP;

    int bh = blockIdx.x;
    int qt = blockIdx.y;
    int h = bh & 7;
    int b = bh >> 3;
    int tid = threadIdx.x;
    int rgrp = tid >> 4;
    int cgrp = tid & 15;
    int q0g = qt * 128;

    const float* Qg = g_q + ((size_t)bh * NN + q0g) * HD;
#pragma unroll
    for (int it = 0; it < 4; it++) {
        int i = tid + it * 512;
        int row = i >> 4, col4 = (i & 15) << 2;
        *(float4*)(sQ + row * KP + col4) = *(const float4*)(Qg + row * HD + col4);
    }

    float mrow[4], lrow[4], o[4][4];
#pragma unroll
    for (int i = 0; i < 4; i++) {
        mrow[i] = -1e30f; lrow[i] = 0.f;
#pragma unroll
        for (int c = 0; c < 4; c++) o[i][c] = 0.f;
    }

    const float* bmat = g_biasmat + ((size_t)h * NN + q0g) * NN;

    for (int kt = 0; kt < 8; kt++) {
        __syncthreads();
        const float* Kg = g_k + ((size_t)bh * NN + kt * 128) * HD;
        const float* Vg = g_v + ((size_t)bh * NN + kt * 128) * HD;
#pragma unroll
        for (int it = 0; it < 4; it++) {
            int i = tid + it * 512;
            int row = i >> 4, col4 = (i & 15) << 2;
            *(float4*)(sK + row * KP + col4) = *(const float4*)(Kg + row * HD + col4);
            *(float4*)(sV + row * KP + col4) = *(const float4*)(Vg + row * HD + col4);
        }
        __syncthreads();

        float s[4][8];
#pragma unroll
        for (int i = 0; i < 4; i++)
#pragma unroll
            for (int j = 0; j < 8; j++) s[i][j] = 0.f;

#pragma unroll 4
        for (int d4 = 0; d4 < HD; d4 += 4) {
            float4 a4[4], b4[8];
#pragma unroll
            for (int i = 0; i < 4; i++)
                a4[i] = *(const float4*)(sQ + (rgrp + 32 * i) * KP + d4);
#pragma unroll
            for (int j = 0; j < 8; j++)
                b4[j] = *(const float4*)(sK + (cgrp + 16 * j) * KP + d4);
#pragma unroll
            for (int i = 0; i < 4; i++)
#pragma unroll
                for (int j = 0; j < 8; j++) {
                    s[i][j] += a4[i].x * b4[j].x;
                    s[i][j] += a4[i].y * b4[j].y;
                    s[i][j] += a4[i].z * b4[j].z;
                    s[i][j] += a4[i].w * b4[j].w;
                }
        }

#pragma unroll
        for (int i = 0; i < 4; i++) {
            const float* bp = bmat + (size_t)(rgrp + 32 * i) * NN + kt * 128 + cgrp;
#pragma unroll
            for (int j = 0; j < 8; j++)
                s[i][j] += __ldg(bp + 16 * j);
        }

#pragma unroll
        for (int i = 0; i < 4; i++) {
            float mt = s[i][0];
#pragma unroll
            for (int j = 1; j < 8; j++) mt = fmaxf(mt, s[i][j]);
#pragma unroll
            for (int off = 8; off; off >>= 1)
                mt = fmaxf(mt, __shfl_xor_sync(0xffffffffu, mt, off, 16));
            float nm = fmaxf(mrow[i], mt);
            float corr = __expf(mrow[i] - nm);
            float ps = 0.f;
#pragma unroll
            for (int j = 0; j < 8; j++) {
                s[i][j] = __expf(s[i][j] - nm);
                ps += s[i][j];
            }
#pragma unroll
            for (int off = 8; off; off >>= 1)
                ps += __shfl_xor_sync(0xffffffffu, ps, off, 16);
            lrow[i] = lrow[i] * corr + ps;
            mrow[i] = nm;
#pragma unroll
            for (int c = 0; c < 4; c++) o[i][c] *= corr;
#pragma unroll
            for (int j = 0; j < 8; j++)
                sS[(rgrp + 32 * i) * SP + cgrp + 16 * j] = s[i][j];
        }
        __syncthreads();

#pragma unroll 4
        for (int k4 = 0; k4 < 128; k4 += 4) {
            float4 p4[4];
#pragma unroll
            for (int i = 0; i < 4; i++)
                p4[i] = *(const float4*)(sS + (rgrp + 32 * i) * SP + k4);
            float4 v4[4];
#pragma unroll
            for (int kk = 0; kk < 4; kk++)
                v4[kk] = *(const float4*)(sV + (k4 + kk) * KP + cgrp * 4);
#pragma unroll
            for (int i = 0; i < 4; i++) {
                o[i][0] += p4[i].x * v4[0].x + p4[i].y * v4[1].x
                         + p4[i].z * v4[2].x + p4[i].w * v4[3].x;
                o[i][1] += p4[i].x * v4[0].y + p4[i].y * v4[1].y
                         + p4[i].z * v4[2].y + p4[i].w * v4[3].y;
                o[i][2] += p4[i].x * v4[0].z + p4[i].y * v4[1].z
                         + p4[i].z * v4[2].z + p4[i].w * v4[3].z;
                o[i][3] += p4[i].x * v4[0].w + p4[i].y * v4[1].w
                         + p4[i].z * v4[2].w + p4[i].w * v4[3].w;
            }
        }
    }

#pragma unroll
    for (int i = 0; i < 4; i++) {
        float inv = 1.f / lrow[i];
        int row = q0g + rgrp + 32 * i;
        float4 ov;
        ov.x = o[i][0] * inv; ov.y = o[i][1] * inv;
        ov.z = o[i][2] * inv; ov.w = o[i][3] * inv;
        *(float4*)(g_attn + ((size_t)b * NN + row) * CC + h * HD + cgrp * 4) = ov;
    }
}

// ----------------------------------------------------------------------------
// launch
// ----------------------------------------------------------------------------
extern "C" void kernel_launch(void* const* d_in, const int* in_sizes, int n_in,
                              void* d_out, int out_size)
{
    int ri = 1;
    while (ri < n_in && in_sizes[ri] != NN * NN) ri++;

    const float* x        = (const float*)d_in[0];
    const int*   relidx   = (const int*)d_in[ri];
    const float* table    = (const float*)d_in[ri + 1];
    const float* seqscale = (const float*)d_in[ri + 2];
    const float* qkv_w    = (const float*)d_in[ri + 3];
    const float* qkv_b    = (const float*)d_in[ri + 4];
    const float* proj_w   = (const float*)d_in[ri + 5];
    const float* proj_b   = (const float*)d_in[ri + 6];
    const float* temp     = (const float*)d_in[ri + 7];
    const float* qemb     = (const float*)d_in[ri + 8];
    const float* fc1w     = (const float*)d_in[ri + 9];
    const float* fc1b     = (const float*)d_in[ri + 10];
    const float* fc2w     = (const float*)d_in[ri + 11];
    const float* fc2b     = (const float*)d_in[ri + 12];
    float* out = (float*)d_out;

    float *qkvbuf, *attnbuf, *ahi, *alo, *whi, *wlo;
    cudaGetSymbolAddress((void**)&qkvbuf, g_qkv);
    cudaGetSymbolAddress((void**)&attnbuf, g_attn);
    cudaGetSymbolAddress((void**)&ahi, g_ahi);
    cudaGetSymbolAddress((void**)&alo, g_alo);
    cudaGetSymbolAddress((void**)&whi, g_whi);
    cudaGetSymbolAddress((void**)&wlo, g_wlo);

    cudaFuncSetAttribute(mma_gemm_kernel,
                         cudaFuncAttributeMaxDynamicSharedMemorySize, GEMM_SMEM);

    // 1) QKV projection (tf32 mma, 3x split)
    split_kernel<<<(M_ROWS * CC / 4 + 255) / 256, 256>>>(x, ahi, alo, M_ROWS * CC / 4);
    split_kernel<<<(3 * CC * CC / 4 + 255) / 256, 256>>>(qkv_w, whi, wlo, 3 * CC * CC / 4);
    {
        dim3 grid(3 * CC / 128, M_ROWS / 128);
        mma_gemm_kernel<<<grid, 256, GEMM_SMEM>>>(ahi, alo, whi, wlo,
                                                  qkv_b, qkvbuf, 3 * CC);
    }

    // 2) CPB MLP -> bias table, then materialize full bias matrix
    cpb_kernel<<<T_ROWS, 512>>>(table, fc1w, fc1b, fc2w, fc2b);
    bias_mat_kernel<<<HEADS * NN * (NN / 4) / 256, 256>>>(relidx);

    // 3) normalize/scale and re-layout
    prep_kernel<<<M_ROWS * HEADS / 8, 256>>>(temp, qemb, seqscale);

    // 4) flash attention
    {
        cudaFuncSetAttribute(attn_kernel,
                             cudaFuncAttributeMaxDynamicSharedMemorySize,
                             ATTN_SMEM);
        dim3 grid(BB * HEADS, NN / 128);
        attn_kernel<<<grid, 512, ATTN_SMEM>>>();
    }

    // 5) output projection (tf32 mma, 3x split)
    split_kernel<<<(M_ROWS * CC / 4 + 255) / 256, 256>>>(attnbuf, ahi, alo, M_ROWS * CC / 4);
    split_kernel<<<(CC * CC / 4 + 255) / 256, 256>>>(proj_w, whi, wlo, CC * CC / 4);
    {
        dim3 grid(CC / 128, M_ROWS / 128);
        mma_gemm_kernel<<<grid, 256, GEMM_SMEM>>>(ahi, alo, whi, wlo,
                                                  proj_b, out, CC);
    }
}

// round 6
// speedup vs baseline: 1.7560x; 1.1528x over previous
#include <cuda_runtime.h>
#include <math.h>
#include <stdint.h>

// Problem constants
#define BB 8
#define NN 1024
#define CC 512
#define HEADS 8
#define HD 64
#define T_ROWS 3969
#define M_ROWS (BB * NN)      // 8192
#define CPB_HIDDEN 512

// ----------------------------------------------------------------------------
// Scratch (static device globals; no runtime allocation)
// ----------------------------------------------------------------------------
__device__ float g_qkv[(size_t)M_ROWS * 3 * CC];
__device__ float g_q[(size_t)BB * HEADS * NN * HD];
__device__ float g_k[(size_t)BB * HEADS * NN * HD];
__device__ float g_v[(size_t)BB * HEADS * NN * HD];
__device__ float g_bias[T_ROWS * HEADS];
__device__ float g_biasmat[(size_t)HEADS * NN * NN];
__device__ float g_attn[(size_t)M_ROWS * CC];
// tf32 split buffers for GEMMs
__device__ float g_ahi[(size_t)M_ROWS * CC];
__device__ float g_alo[(size_t)M_ROWS * CC];
__device__ float g_whi[(size_t)3 * CC * CC];
__device__ float g_wlo[(size_t)3 * CC * CC];

// ----------------------------------------------------------------------------
// tf32 helpers
// ----------------------------------------------------------------------------
__device__ __forceinline__ float tf32_rna(float v) {
    uint32_t r;
    asm("cvt.rna.tf32.f32 %0, %1;" : "=r"(r) : "f"(v));
    return __uint_as_float(r);
}

__device__ __forceinline__ void mma_tf32(float* d, uint32_t a0, uint32_t a1,
                                         uint32_t a2, uint32_t a3,
                                         uint32_t b0, uint32_t b1) {
    asm volatile(
        "mma.sync.aligned.m16n8k8.row.col.f32.tf32.tf32.f32 "
        "{%0,%1,%2,%3}, {%4,%5,%6,%7}, {%8,%9}, {%0,%1,%2,%3};"
        : "+f"(d[0]), "+f"(d[1]), "+f"(d[2]), "+f"(d[3])
        : "r"(a0), "r"(a1), "r"(a2), "r"(a3), "r"(b0), "r"(b1));
}

// split float into tf32 hi (rna bits) + lo (residual, raw fp32 bits; HW truncates)
__device__ __forceinline__ void split2(float v, uint32_t& hi, uint32_t& lo) {
    float h = tf32_rna(v);
    hi = __float_as_uint(h);
    lo = __float_as_uint(v - h);
}

// ----------------------------------------------------------------------------
// Split a float array into tf32 hi/lo parts (float4 elementwise)
// ----------------------------------------------------------------------------
__global__ __launch_bounds__(256) void split_kernel(
    const float* __restrict__ src, float* __restrict__ hi,
    float* __restrict__ lo, int n4)
{
    int i = blockIdx.x * 256 + threadIdx.x;
    if (i >= n4) return;
    float4 v = *(const float4*)(src + i * 4);
    float4 h, l;
    h.x = tf32_rna(v.x); l.x = v.x - h.x;
    h.y = tf32_rna(v.y); l.y = v.y - h.y;
    h.z = tf32_rna(v.z); l.z = v.z - h.z;
    h.w = tf32_rna(v.w); l.w = v.w - h.w;
    *(float4*)(hi + i * 4) = h;
    *(float4*)(lo + i * 4) = l;
}

// ----------------------------------------------------------------------------
// tf32 mma GEMM (3x split): C[M,Nn] = A[M,512] @ W[Nn,512]^T + bias[Nn]
// CTA 128x128, BK=32, 8 warps of 32x64 (2 m16-frags x 8 n8-frags).
// ----------------------------------------------------------------------------
#define GP 36
#define GEMM_SMEM (4 * 128 * GP * 4)

__global__ __launch_bounds__(256, 1)
void mma_gemm_kernel(const float* __restrict__ Ahi, const float* __restrict__ Alo,
                     const float* __restrict__ Bhi, const float* __restrict__ Blo,
                     const float* __restrict__ bias, float* __restrict__ C, int Nn)
{
    extern __shared__ float sm[];
    float* sAh = sm;
    float* sAl = sm + 128 * GP;
    float* sBh = sm + 2 * 128 * GP;
    float* sBl = sm + 3 * 128 * GP;

    int tid = threadIdx.x;
    int wid = tid >> 5, lane = tid & 31;
    int g = lane >> 2, t = lane & 3;
    int wm = (wid & 3) * 32;
    int wn = (wid >> 2) * 64;
    int m0 = blockIdx.y * 128, n0 = blockIdx.x * 128;

    float d[2][8][4];
#pragma unroll
    for (int mt = 0; mt < 2; mt++)
#pragma unroll
        for (int nt = 0; nt < 8; nt++)
#pragma unroll
            for (int r = 0; r < 4; r++) d[mt][nt][r] = 0.f;

    for (int ch = 0; ch < 16; ch++) {
        __syncthreads();
#pragma unroll
        for (int it = 0; it < 4; it++) {
            int idx = tid + it * 256;
            int m = idx >> 3, k4 = (idx & 7) << 2;
            size_t goff = (size_t)(m0 + m) * 512 + ch * 32 + k4;
            size_t boff = (size_t)(n0 + m) * 512 + ch * 32 + k4;
            *(float4*)(sAh + m * GP + k4) = *(const float4*)(Ahi + goff);
            *(float4*)(sAl + m * GP + k4) = *(const float4*)(Alo + goff);
            *(float4*)(sBh + m * GP + k4) = *(const float4*)(Bhi + boff);
            *(float4*)(sBl + m * GP + k4) = *(const float4*)(Blo + boff);
        }
        __syncthreads();

#pragma unroll
        for (int ks = 0; ks < 4; ks++) {
            uint32_t ah[2][4], al[2][4];
#pragma unroll
            for (int mt = 0; mt < 2; mt++) {
                const float* p = sAh + (wm + mt * 16 + g) * GP + ks * 8 + t;
                const float* q = sAl + (wm + mt * 16 + g) * GP + ks * 8 + t;
                ah[mt][0] = __float_as_uint(p[0]);
                ah[mt][1] = __float_as_uint(p[8 * GP]);
                ah[mt][2] = __float_as_uint(p[4]);
                ah[mt][3] = __float_as_uint(p[8 * GP + 4]);
                al[mt][0] = __float_as_uint(q[0]);
                al[mt][1] = __float_as_uint(q[8 * GP]);
                al[mt][2] = __float_as_uint(q[4]);
                al[mt][3] = __float_as_uint(q[8 * GP + 4]);
            }
            uint32_t bh[8][2], bl[8][2];
#pragma unroll
            for (int nt = 0; nt < 8; nt++) {
                const float* p = sBh + (wn + nt * 8 + g) * GP + ks * 8 + t;
                const float* q = sBl + (wn + nt * 8 + g) * GP + ks * 8 + t;
                bh[nt][0] = __float_as_uint(p[0]);
                bh[nt][1] = __float_as_uint(p[4]);
                bl[nt][0] = __float_as_uint(q[0]);
                bl[nt][1] = __float_as_uint(q[4]);
            }
#pragma unroll
            for (int mt = 0; mt < 2; mt++)
#pragma unroll
                for (int nt = 0; nt < 8; nt++) {
                    mma_tf32(d[mt][nt], ah[mt][0], ah[mt][1], ah[mt][2], ah[mt][3],
                             bh[nt][0], bh[nt][1]);
                    mma_tf32(d[mt][nt], ah[mt][0], ah[mt][1], ah[mt][2], ah[mt][3],
                             bl[nt][0], bl[nt][1]);
                    mma_tf32(d[mt][nt], al[mt][0], al[mt][1], al[mt][2], al[mt][3],
                             bh[nt][0], bh[nt][1]);
                }
        }
    }

#pragma unroll
    for (int nt = 0; nt < 8; nt++) {
        int col = n0 + wn + nt * 8 + 2 * t;
        float b0 = bias[col], b1 = bias[col + 1];
#pragma unroll
        for (int mt = 0; mt < 2; mt++) {
            int row = m0 + wm + mt * 16 + g;
            float2 v0 = make_float2(d[mt][nt][0] + b0, d[mt][nt][1] + b1);
            float2 v1 = make_float2(d[mt][nt][2] + b0, d[mt][nt][3] + b1);
            *(float2*)(C + (size_t)row * Nn + col) = v0;
            *(float2*)(C + (size_t)(row + 8) * Nn + col) = v1;
        }
    }
}

// ----------------------------------------------------------------------------
// CPB MLP
// ----------------------------------------------------------------------------
__global__ __launch_bounds__(512) void cpb_kernel(
    const float* __restrict__ table,
    const float* __restrict__ fc1w, const float* __restrict__ fc1b,
    const float* __restrict__ fc2w, const float* __restrict__ fc2b)
{
    __shared__ float sh[CPB_HIDDEN];
    __shared__ float part[16];
    int t = blockIdx.x;
    int tid = threadIdx.x;

    float c0 = table[t * 2 + 0];
    float c1 = table[t * 2 + 1];
    float hv = c0 * fc1w[tid * 2 + 0] + c1 * fc1w[tid * 2 + 1] + fc1b[tid];
    sh[tid] = fmaxf(hv, 0.f);
    __syncthreads();

    int w = tid >> 5, lane = tid & 31;
    int head = w & 7, seg = w >> 3;
    float s = 0.f;
#pragma unroll
    for (int i = 0; i < 8; i++) {
        int j = seg * 256 + i * 32 + lane;
        s += sh[j] * fc2w[head * CPB_HIDDEN + j];
    }
#pragma unroll
    for (int off = 16; off; off >>= 1)
        s += __shfl_xor_sync(0xffffffffu, s, off);
    if (lane == 0) part[w] = s;
    __syncthreads();
    if (tid < 8) g_bias[t * 8 + tid] = part[tid] + part[tid + 8] + fc2b[tid];
}

// ----------------------------------------------------------------------------
// Materialize bias matrix
// ----------------------------------------------------------------------------
__global__ __launch_bounds__(256) void bias_mat_kernel(const int* __restrict__ relidx)
{
    int gid = blockIdx.x * 256 + threadIdx.x;
    int m4 = gid & 255;
    int n  = (gid >> 8) & 1023;
    int h  = gid >> 18;
    int4 idx = *(const int4*)(relidx + (size_t)n * NN + m4 * 4);
    float4 o;
    o.x = g_bias[idx.x * 8 + h];
    o.y = g_bias[idx.y * 8 + h];
    o.z = g_bias[idx.z * 8 + h];
    o.w = g_bias[idx.w * 8 + h];
    *(float4*)(g_biasmat + ((size_t)h * NN + n) * NN + m4 * 4) = o;
}

// ----------------------------------------------------------------------------
// Prep: split qkv per-(b,h); L2-normalize q,k; scale q.
// ----------------------------------------------------------------------------
__global__ __launch_bounds__(256) void prep_kernel(
    const float* __restrict__ temperature,
    const float* __restrict__ query_emb,
    const float* __restrict__ seq_scale)
{
    int gid = blockIdx.x * 8 + (threadIdx.x >> 5);
    int lane = threadIdx.x & 31;
    int m = gid >> 3, h = gid & 7;
    int b = m >> 10, n = m & 1023;

    const float* src = g_qkv + (size_t)m * (3 * CC) + h * HD;
    float q0 = src[lane],           q1 = src[lane + 32];
    float k0 = src[CC + lane],      k1 = src[CC + lane + 32];
    float v0 = src[2 * CC + lane],  v1 = src[2 * CC + lane + 32];

    float sq = q0 * q0 + q1 * q1;
    float sk = k0 * k0 + k1 * k1;
#pragma unroll
    for (int off = 16; off; off >>= 1) {
        sq += __shfl_xor_sync(0xffffffffu, sq, off);
        sk += __shfl_xor_sync(0xffffffffu, sk, off);
    }
    float qinv = 1.f / fmaxf(sqrtf(sq), 1e-12f);
    float kinv = 1.f / fmaxf(sqrtf(sk), 1e-12f);

    float tv = temperature[h];
    float sp = (tv > 20.f) ? tv : log1pf(expf(tv));
    float scale = sp * seq_scale[0];

    size_t dst = ((size_t)(b * 8 + h) * NN + n) * HD;
    g_q[dst + lane]      = (q0 * qinv + query_emb[h * HD + lane]) * scale;
    g_q[dst + lane + 32] = (q1 * qinv + query_emb[h * HD + lane + 32]) * scale;
    g_k[dst + lane]      = k0 * kinv;
    g_k[dst + lane + 32] = k1 * kinv;
    g_v[dst + lane]      = v0;
    g_v[dst + lane + 32] = v1;
}

// ----------------------------------------------------------------------------
// Flash attention on tf32 mma (3x split), 128q x 128k tile, 256 threads.
// Each warp owns 16 q-rows x full 128-key tile (softmax entirely in-warp).
// QK^T: A=Q frags, B=K frags; P stored per-warp in sP; PV: A=P, B=V.
// Pitches: Q/K 68, V 72, P 132 -> conflict-free fragment loads.
// ----------------------------------------------------------------------------
#define QP 68
#define KPP 68
#define VP 72
#define PP 132
#define ATTN_SMEM ((128 * QP + 128 * KPP + 128 * VP + 128 * PP) * 4)

__global__ __launch_bounds__(256, 1) void attn_kernel()
{
    extern __shared__ float sm[];
    float* sQ = sm;
    float* sK = sQ + 128 * QP;
    float* sV = sK + 128 * KPP;
    float* sP = sV + 128 * VP;

    int bh = blockIdx.x;          // 0..63
    int qt = blockIdx.y;          // 0..7
    int h = bh & 7, b = bh >> 3;
    int tid = threadIdx.x;
    int wid = tid >> 5, lane = tid & 31;
    int g = lane >> 2, t = lane & 3;
    int q0g = qt * 128;
    int wrow = wid * 16;          // warp's 16-row block in tile

    // stage Q tile (128 x 64)
    const float* Qg = g_q + ((size_t)bh * NN + q0g) * HD;
#pragma unroll
    for (int it = 0; it < 8; it++) {
        int i = tid + it * 256;
        int row = i >> 4, c4 = (i & 15) << 2;
        *(float4*)(sQ + row * QP + c4) = *(const float4*)(Qg + row * HD + c4);
    }

    float o[8][4];
#pragma unroll
    for (int nt = 0; nt < 8; nt++)
#pragma unroll
        for (int r = 0; r < 4; r++) o[nt][r] = 0.f;
    float mrow0 = -1e30f, mrow1 = -1e30f, lrow0 = 0.f, lrow1 = 0.f;

    const float* bmat = g_biasmat + ((size_t)h * NN + q0g) * NN;

    for (int kt = 0; kt < 8; kt++) {
        __syncthreads();
        const float* Kg = g_k + ((size_t)bh * NN + kt * 128) * HD;
        const float* Vg = g_v + ((size_t)bh * NN + kt * 128) * HD;
#pragma unroll
        for (int it = 0; it < 8; it++) {
            int i = tid + it * 256;
            int row = i >> 4, c4 = (i & 15) << 2;
            *(float4*)(sK + row * KPP + c4) = *(const float4*)(Kg + row * HD + c4);
            *(float4*)(sV + row * VP + c4)  = *(const float4*)(Vg + row * HD + c4);
        }
        __syncthreads();

        // ---- QK^T: scores c[16][4] over 128 keys ----
        float c[16][4];
#pragma unroll
        for (int nt = 0; nt < 16; nt++)
#pragma unroll
            for (int r = 0; r < 4; r++) c[nt][r] = 0.f;

#pragma unroll
        for (int ks = 0; ks < 8; ks++) {
            float a0 = sQ[(wrow + g) * QP + ks * 8 + t];
            float a1 = sQ[(wrow + g + 8) * QP + ks * 8 + t];
            float a2 = sQ[(wrow + g) * QP + ks * 8 + t + 4];
            float a3 = sQ[(wrow + g + 8) * QP + ks * 8 + t + 4];
            uint32_t ah0, ah1, ah2, ah3, al0, al1, al2, al3;
            split2(a0, ah0, al0); split2(a1, ah1, al1);
            split2(a2, ah2, al2); split2(a3, ah3, al3);
#pragma unroll
            for (int nt = 0; nt < 16; nt++) {
                float b0 = sK[(nt * 8 + g) * KPP + ks * 8 + t];
                float b1 = sK[(nt * 8 + g) * KPP + ks * 8 + t + 4];
                uint32_t bh0, bh1, bl0, bl1;
                split2(b0, bh0, bl0); split2(b1, bh1, bl1);
                mma_tf32(c[nt], ah0, ah1, ah2, ah3, bh0, bh1);
                mma_tf32(c[nt], ah0, ah1, ah2, ah3, bl0, bl1);
                mma_tf32(c[nt], al0, al1, al2, al3, bh0, bh1);
            }
        }

        // ---- bias add ----
#pragma unroll
        for (int nt = 0; nt < 16; nt++) {
            const float* bp = bmat + (size_t)(wrow + g) * NN + kt * 128 + nt * 8 + 2 * t;
            float2 b0 = *(const float2*)bp;
            float2 b1 = *(const float2*)(bp + (size_t)8 * NN);
            c[nt][0] += b0.x; c[nt][1] += b0.y;
            c[nt][2] += b1.x; c[nt][3] += b1.y;
        }

        // ---- online softmax (rows g and g+8, in-warp quad reductions) ----
        float mt0 = -1e30f, mt1 = -1e30f;
#pragma unroll
        for (int nt = 0; nt < 16; nt++) {
            mt0 = fmaxf(mt0, fmaxf(c[nt][0], c[nt][1]));
            mt1 = fmaxf(mt1, fmaxf(c[nt][2], c[nt][3]));
        }
        mt0 = fmaxf(mt0, __shfl_xor_sync(0xffffffffu, mt0, 1));
        mt0 = fmaxf(mt0, __shfl_xor_sync(0xffffffffu, mt0, 2));
        mt1 = fmaxf(mt1, __shfl_xor_sync(0xffffffffu, mt1, 1));
        mt1 = fmaxf(mt1, __shfl_xor_sync(0xffffffffu, mt1, 2));

        float nm0 = fmaxf(mrow0, mt0), nm1 = fmaxf(mrow1, mt1);
        float corr0 = __expf(mrow0 - nm0), corr1 = __expf(mrow1 - nm1);
        mrow0 = nm0; mrow1 = nm1;

        float ps0 = 0.f, ps1 = 0.f;
#pragma unroll
        for (int nt = 0; nt < 16; nt++) {
            c[nt][0] = __expf(c[nt][0] - nm0); ps0 += c[nt][0];
            c[nt][1] = __expf(c[nt][1] - nm0); ps0 += c[nt][1];
            c[nt][2] = __expf(c[nt][2] - nm1); ps1 += c[nt][2];
            c[nt][3] = __expf(c[nt][3] - nm1); ps1 += c[nt][3];
        }
        ps0 += __shfl_xor_sync(0xffffffffu, ps0, 1);
        ps0 += __shfl_xor_sync(0xffffffffu, ps0, 2);
        ps1 += __shfl_xor_sync(0xffffffffu, ps1, 1);
        ps1 += __shfl_xor_sync(0xffffffffu, ps1, 2);
        lrow0 = lrow0 * corr0 + ps0;
        lrow1 = lrow1 * corr1 + ps1;

#pragma unroll
        for (int nt = 0; nt < 8; nt++) {
            o[nt][0] *= corr0; o[nt][1] *= corr0;
            o[nt][2] *= corr1; o[nt][3] *= corr1;
        }

        // ---- store P (warp-private rows) ----
#pragma unroll
        for (int nt = 0; nt < 16; nt++) {
            *(float2*)(sP + (wrow + g) * PP + nt * 8 + 2 * t) =
                make_float2(c[nt][0], c[nt][1]);
            *(float2*)(sP + (wrow + g + 8) * PP + nt * 8 + 2 * t) =
                make_float2(c[nt][2], c[nt][3]);
        }
        __syncwarp();

        // ---- PV: o[8 n-frags over 64 dims] += P[16 x 128] @ V[128 x 64] ----
#pragma unroll
        for (int kk = 0; kk < 16; kk++) {
            float p0 = sP[(wrow + g) * PP + kk * 8 + t];
            float p1 = sP[(wrow + g + 8) * PP + kk * 8 + t];
            float p2 = sP[(wrow + g) * PP + kk * 8 + t + 4];
            float p3 = sP[(wrow + g + 8) * PP + kk * 8 + t + 4];
            uint32_t ph0, ph1, ph2, ph3, pl0, pl1, pl2, pl3;
            split2(p0, ph0, pl0); split2(p1, ph1, pl1);
            split2(p2, ph2, pl2); split2(p3, ph3, pl3);
#pragma unroll
            for (int nt = 0; nt < 8; nt++) {
                float v0 = sV[(kk * 8 + t) * VP + nt * 8 + g];
                float v1 = sV[(kk * 8 + t + 4) * VP + nt * 8 + g];
                uint32_t vh0, vh1, vl0, vl1;
                split2(v0, vh0, vl0); split2(v1, vh1, vl1);
                mma_tf32(o[nt], ph0, ph1, ph2, ph3, vh0, vh1);
                mma_tf32(o[nt], ph0, ph1, ph2, ph3, vl0, vl1);
                mma_tf32(o[nt], pl0, pl1, pl2, pl3, vh0, vh1);
            }
        }
        __syncwarp();
    }

    // epilogue: normalize, write (b,n,h,d)
    float inv0 = 1.f / lrow0, inv1 = 1.f / lrow1;
    int row0 = q0g + wrow + g;
#pragma unroll
    for (int nt = 0; nt < 8; nt++) {
        int col = h * HD + nt * 8 + 2 * t;
        *(float2*)(g_attn + ((size_t)b * NN + row0) * CC + col) =
            make_float2(o[nt][0] * inv0, o[nt][1] * inv0);
        *(float2*)(g_attn + ((size_t)b * NN + row0 + 8) * CC + col) =
            make_float2(o[nt][2] * inv1, o[nt][3] * inv1);
    }
}

// ----------------------------------------------------------------------------
// launch
// ----------------------------------------------------------------------------
extern "C" void kernel_launch(void* const* d_in, const int* in_sizes, int n_in,
                              void* d_out, int out_size)
{
    int ri = 1;
    while (ri < n_in && in_sizes[ri] != NN * NN) ri++;

    const float* x        = (const float*)d_in[0];
    const int*   relidx   = (const int*)d_in[ri];
    const float* table    = (const float*)d_in[ri + 1];
    const float* seqscale = (const float*)d_in[ri + 2];
    const float* qkv_w    = (const float*)d_in[ri + 3];
    const float* qkv_b    = (const float*)d_in[ri + 4];
    const float* proj_w   = (const float*)d_in[ri + 5];
    const float* proj_b   = (const float*)d_in[ri + 6];
    const float* temp     = (const float*)d_in[ri + 7];
    const float* qemb     = (const float*)d_in[ri + 8];
    const float* fc1w     = (const float*)d_in[ri + 9];
    const float* fc1b     = (const float*)d_in[ri + 10];
    const float* fc2w     = (const float*)d_in[ri + 11];
    const float* fc2b     = (const float*)d_in[ri + 12];
    float* out = (float*)d_out;

    float *qkvbuf, *attnbuf, *ahi, *alo, *whi, *wlo;
    cudaGetSymbolAddress((void**)&qkvbuf, g_qkv);
    cudaGetSymbolAddress((void**)&attnbuf, g_attn);
    cudaGetSymbolAddress((void**)&ahi, g_ahi);
    cudaGetSymbolAddress((void**)&alo, g_alo);
    cudaGetSymbolAddress((void**)&whi, g_whi);
    cudaGetSymbolAddress((void**)&wlo, g_wlo);

    cudaFuncSetAttribute(mma_gemm_kernel,
                         cudaFuncAttributeMaxDynamicSharedMemorySize, GEMM_SMEM);

    // 1) QKV projection (tf32 mma, 3x split)
    split_kernel<<<(M_ROWS * CC / 4 + 255) / 256, 256>>>(x, ahi, alo, M_ROWS * CC / 4);
    split_kernel<<<(3 * CC * CC / 4 + 255) / 256, 256>>>(qkv_w, whi, wlo, 3 * CC * CC / 4);
    {
        dim3 grid(3 * CC / 128, M_ROWS / 128);
        mma_gemm_kernel<<<grid, 256, GEMM_SMEM>>>(ahi, alo, whi, wlo,
                                                  qkv_b, qkvbuf, 3 * CC);
    }

    // 2) CPB MLP -> bias table, then materialize full bias matrix
    cpb_kernel<<<T_ROWS, 512>>>(table, fc1w, fc1b, fc2w, fc2b);
    bias_mat_kernel<<<HEADS * NN * (NN / 4) / 256, 256>>>(relidx);

    // 3) normalize/scale and re-layout
    prep_kernel<<<M_ROWS * HEADS / 8, 256>>>(temp, qemb, seqscale);

    // 4) flash attention (tf32 mma)
    {
        cudaFuncSetAttribute(attn_kernel,
                             cudaFuncAttributeMaxDynamicSharedMemorySize,
                             ATTN_SMEM);
        dim3 grid(BB * HEADS, NN / 128);
        attn_kernel<<<grid, 256, ATTN_SMEM>>>();
    }

    // 5) output projection (tf32 mma, 3x split)
    split_kernel<<<(M_ROWS * CC / 4 + 255) / 256, 256>>>(attnbuf, ahi, alo, M_ROWS * CC / 4);
    split_kernel<<<(CC * CC / 4 + 255) / 256, 256>>>(proj_w, whi, wlo, CC * CC / 4);
    {
        dim3 grid(CC / 128, M_ROWS / 128);
        mma_gemm_kernel<<<grid, 256, GEMM_SMEM>>>(ahi, alo, whi, wlo,
                                                  proj_b, out, CC);
    }
}